// round 1
// baseline (speedup 1.0000x reference)
#include <cuda_runtime.h>

// Problem constants
#define NB   64
#define NH   32
#define NW   32
#define ND   384
#define NBHW (NB*NH*NW)          // 65536 rows

// Scratch (device globals; no allocation allowed)
__device__ float g_p[NBHW * 4];                 // [b,h,w][yh0,yh1,yw0,yw1]
__device__ float g_attn_h[NB * NW * 32 * 32];   // [b][w][h1][h2]
__device__ float g_attn_w[NB * NH * 32 * 32];   // [b][h][w1][w2]
__device__ float g_Yhw[(size_t)NBHW * ND];      // Yh + Yw
__device__ float g_Wco[ND * ND];                // Wo @ Wc
__device__ float g_bias[ND];                    // Wo @ bc + bo

// ---------------------------------------------------------------------------
// Wco[o][d] = sum_k Wo[o][k] * Wc[k][d]
__global__ void wco_kernel(const float* __restrict__ Wo, const float* __restrict__ Wc) {
    __shared__ float As[16][16];
    __shared__ float Bs[16][17];
    int o = blockIdx.y * 16 + threadIdx.y;
    int d = blockIdx.x * 16 + threadIdx.x;
    float acc = 0.f;
    for (int k0 = 0; k0 < ND; k0 += 16) {
        As[threadIdx.y][threadIdx.x] = Wo[o * ND + k0 + threadIdx.x];
        Bs[threadIdx.y][threadIdx.x] = Wc[(k0 + threadIdx.y) * ND + d];
        __syncthreads();
#pragma unroll
        for (int k = 0; k < 16; k++) acc += As[threadIdx.y][k] * Bs[k][threadIdx.x];
        __syncthreads();
    }
    g_Wco[o * ND + d] = acc;
}

// bias[o] = bo[o] + sum_k Wo[o][k]*bc[k]
__global__ void bias_kernel(const float* __restrict__ Wo, const float* __restrict__ bc,
                            const float* __restrict__ bo) {
    int o = threadIdx.x;
    float s = bo[o];
    for (int k = 0; k < ND; k++) s += Wo[o * ND + k] * bc[k];
    g_bias[o] = s;
}

// ---------------------------------------------------------------------------
// Projections: p[row][0..1] = x[row]·W1h[e] + b1h[e]; p[row][2..3] = x[row]·W1w[e] + b1w[e]
__global__ __launch_bounds__(256) void proj_kernel(
    const float* __restrict__ x,
    const float* __restrict__ W1h, const float* __restrict__ b1h,
    const float* __restrict__ W1w, const float* __restrict__ b1w) {
    __shared__ __align__(16) float sW[1536];
    int tid = threadIdx.x;
    for (int i = tid; i < 768; i += 256) sW[i] = W1h[i];
    for (int i = tid; i < 768; i += 256) sW[768 + i] = W1w[i];
    __syncthreads();
    int lane = tid & 31, warp = tid >> 5;
    int row = blockIdx.x * 8 + warp;
    const float4* xr = (const float4*)(x + (size_t)row * ND);
    const float4* w0 = (const float4*)(sW);
    const float4* w1 = (const float4*)(sW + 384);
    const float4* w2 = (const float4*)(sW + 768);
    const float4* w3 = (const float4*)(sW + 1152);
    float a0 = 0.f, a1 = 0.f, a2 = 0.f, a3 = 0.f;
#pragma unroll
    for (int j = 0; j < 3; j++) {
        float4 xv = xr[lane + j * 32];
        float4 v;
        v = w0[lane + j * 32]; a0 += xv.x*v.x + xv.y*v.y + xv.z*v.z + xv.w*v.w;
        v = w1[lane + j * 32]; a1 += xv.x*v.x + xv.y*v.y + xv.z*v.z + xv.w*v.w;
        v = w2[lane + j * 32]; a2 += xv.x*v.x + xv.y*v.y + xv.z*v.z + xv.w*v.w;
        v = w3[lane + j * 32]; a3 += xv.x*v.x + xv.y*v.y + xv.z*v.z + xv.w*v.w;
    }
#pragma unroll
    for (int off = 16; off; off >>= 1) {
        a0 += __shfl_xor_sync(~0u, a0, off);
        a1 += __shfl_xor_sync(~0u, a1, off);
        a2 += __shfl_xor_sync(~0u, a2, off);
        a3 += __shfl_xor_sync(~0u, a3, off);
    }
    if (lane == 0) {
        float* pp = g_p + (size_t)row * 4;
        pp[0] = a0 + b1h[0];
        pp[1] = a1 + b1h[1];
        pp[2] = a2 + b1w[0];
        pp[3] = a3 + b1w[1];
    }
}

// ---------------------------------------------------------------------------
// Grouped mix logits + softmax.
// which=0 (h-mix): blk=(b,w), channels e*32+h, out g_attn_h[b][w][h1][h2]
// which=1 (w-mix): blk=(b,h), channels e*32+w, out g_attn_w[b][h][w1][w2]
__global__ __launch_bounds__(1024) void attn_kernel(
    const float* __restrict__ W2, const float* __restrict__ b2, int which) {
    int blk = blockIdx.x;
    int b = blk >> 5, s = blk & 31;
    int tid = threadIdx.x;
    __shared__ float yv[64];
    if (tid < 64) {
        int e = tid >> 5, t = tid & 31;
        int h = which ? s : t;
        int w = which ? t : s;
        yv[tid] = g_p[(size_t)(((b * 32 + h) * 32 + w) << 2) + (which ? 2 : 0) + e];
    }
    __syncthreads();
    int g = tid >> 7;
    float z = b2[tid];
    const float* wr = W2 + tid * 8;
    const float* yb = yv + g * 8;
#pragma unroll
    for (int c = 0; c < 8; c++) z += yb[c] * wr[c];
    float m = z;
#pragma unroll
    for (int off = 16; off; off >>= 1) m = fmaxf(m, __shfl_xor_sync(~0u, m, off));
    float ez = __expf(z - m);
    float sum = ez;
#pragma unroll
    for (int off = 16; off; off >>= 1) sum += __shfl_xor_sync(~0u, sum, off);
    float* out = which ? g_attn_w : g_attn_h;
    out[(size_t)blk * 1024 + tid] = ez * (1.0f / sum);
}

// ---------------------------------------------------------------------------
// Apply attention mixes.
// which=0: blk=(b,h): Yhw[b,h,i,d]  = sum_j attn_w[b,h,i,j] * x[b,h,j,d]   (write)
// which=1: blk=(b,w): Yhw[b,i,w,d] += sum_j attn_h[b,w,i,j] * x[b,j,w,d]   (accumulate)
__global__ __launch_bounds__(384) void mix_apply_kernel(const float* __restrict__ x, int which) {
    __shared__ __align__(16) float Ast[32 * 32];  // Ast[j*32 + i]
    int blk = blockIdx.x;
    int b = blk >> 5, s = blk & 31;
    int tid = threadIdx.x;  // 384 threads, one output column each
    const float* attn = (which ? g_attn_h : g_attn_w) + (size_t)blk * 1024;
    for (int idx = tid; idx < 1024; idx += 384) {
        int i = idx >> 5, j = idx & 31;
        Ast[j * 32 + i] = attn[idx];
    }
    __syncthreads();

    const float* xp;
    size_t xstride;
    if (which == 0) { xp = x + (size_t)blk * (32 * ND) + tid; xstride = ND; }
    else            { xp = x + ((size_t)b * 1024 + s) * ND + tid; xstride = (size_t)32 * ND; }

    float acc[32];
#pragma unroll
    for (int i = 0; i < 32; i++) acc[i] = 0.f;

#pragma unroll 8
    for (int j = 0; j < 32; j++) {
        float xv = xp[(size_t)j * xstride];
        const float4* a4 = (const float4*)(Ast + j * 32);
#pragma unroll
        for (int i4 = 0; i4 < 8; i4++) {
            float4 a = a4[i4];
            acc[i4 * 4 + 0] += a.x * xv;
            acc[i4 * 4 + 1] += a.y * xv;
            acc[i4 * 4 + 2] += a.z * xv;
            acc[i4 * 4 + 3] += a.w * xv;
        }
    }
    if (which == 0) {
        float* yb = g_Yhw + (size_t)blk * (32 * ND) + tid;
#pragma unroll
        for (int i = 0; i < 32; i++) yb[(size_t)i * ND] = acc[i];
    } else {
        float* yb = g_Yhw + ((size_t)b * 1024 + s) * ND + tid;
#pragma unroll
        for (int i = 0; i < 32; i++) yb[(size_t)i * 32 * ND] += acc[i];
    }
}

// ---------------------------------------------------------------------------
// Final fused GEMM: out[m,o] = sum_d Yhw[m,d]*Wo[o,d] + sum_d x[m,d]*Wco[o,d] + bias[o]
#define BM 128
#define BN 128
#define BK 8
__global__ __launch_bounds__(256) void gemm_kernel(
    const float* __restrict__ x, const float* __restrict__ Wo, float* __restrict__ out) {
    __shared__ float As[BK][BM];
    __shared__ float Bs[BK][BN];
    int tid = threadIdx.x;
    int m0 = blockIdx.y * BM;
    int n0 = blockIdx.x * BN;
    int lr = tid >> 1;          // 0..127
    int lc = (tid & 1) * 4;     // 0 or 4
    int tx = tid & 15, ty = tid >> 4;

    float acc[8][8];
#pragma unroll
    for (int i = 0; i < 8; i++)
#pragma unroll
        for (int j = 0; j < 8; j++) acc[i][j] = 0.f;

#pragma unroll 1
    for (int phase = 0; phase < 2; phase++) {
        const float* A = phase ? x : g_Yhw;
        const float* B = phase ? g_Wco : Wo;
#pragma unroll 1
        for (int k0 = 0; k0 < ND; k0 += BK) {
            float4 av = *(const float4*)(A + (size_t)(m0 + lr) * ND + k0 + lc);
            float4 bv = *(const float4*)(B + (size_t)(n0 + lr) * ND + k0 + lc);
            __syncthreads();
            As[lc + 0][lr] = av.x; As[lc + 1][lr] = av.y;
            As[lc + 2][lr] = av.z; As[lc + 3][lr] = av.w;
            Bs[lc + 0][lr] = bv.x; Bs[lc + 1][lr] = bv.y;
            Bs[lc + 2][lr] = bv.z; Bs[lc + 3][lr] = bv.w;
            __syncthreads();
#pragma unroll
            for (int k = 0; k < BK; k++) {
                float4 m0v = *(const float4*)(&As[k][ty * 8]);
                float4 m1v = *(const float4*)(&As[k][ty * 8 + 4]);
                float4 n0v = *(const float4*)(&Bs[k][tx * 8]);
                float4 n1v = *(const float4*)(&Bs[k][tx * 8 + 4]);
                float rm[8] = {m0v.x, m0v.y, m0v.z, m0v.w, m1v.x, m1v.y, m1v.z, m1v.w};
                float rn[8] = {n0v.x, n0v.y, n0v.z, n0v.w, n1v.x, n1v.y, n1v.z, n1v.w};
#pragma unroll
                for (int i = 0; i < 8; i++)
#pragma unroll
                    for (int j = 0; j < 8; j++) acc[i][j] += rm[i] * rn[j];
            }
        }
    }

    float bn[8];
#pragma unroll
    for (int j = 0; j < 8; j++) bn[j] = g_bias[n0 + tx * 8 + j];
#pragma unroll
    for (int i = 0; i < 8; i++) {
        size_t off = (size_t)(m0 + ty * 8 + i) * ND + n0 + tx * 8;
        float4 v0 = {acc[i][0] + bn[0], acc[i][1] + bn[1], acc[i][2] + bn[2], acc[i][3] + bn[3]};
        float4 v1 = {acc[i][4] + bn[4], acc[i][5] + bn[5], acc[i][6] + bn[6], acc[i][7] + bn[7]};
        *(float4*)(out + off) = v0;
        *(float4*)(out + off + 4) = v1;
    }
}

// ---------------------------------------------------------------------------
extern "C" void kernel_launch(void* const* d_in, const int* in_sizes, int n_in,
                              void* d_out, int out_size) {
    const float* x   = (const float*)d_in[0];
    const float* Wc  = (const float*)d_in[1];
    const float* bc  = (const float*)d_in[2];
    const float* Wo  = (const float*)d_in[3];
    const float* bo  = (const float*)d_in[4];
    const float* W1h = (const float*)d_in[5];
    const float* b1h = (const float*)d_in[6];
    const float* W2h = (const float*)d_in[7];
    const float* b2h = (const float*)d_in[8];
    const float* W1w = (const float*)d_in[9];
    const float* b1w = (const float*)d_in[10];
    const float* W2w = (const float*)d_in[11];
    const float* b2w = (const float*)d_in[12];
    float* out = (float*)d_out;

    wco_kernel<<<dim3(24, 24), dim3(16, 16)>>>(Wo, Wc);
    bias_kernel<<<1, 384>>>(Wo, bc, bo);
    proj_kernel<<<NBHW / 8, 256>>>(x, W1h, b1h, W1w, b1w);
    attn_kernel<<<NB * NW, 1024>>>(W2h, b2h, 0);
    attn_kernel<<<NB * NH, 1024>>>(W2w, b2w, 1);
    mix_apply_kernel<<<NB * NH, 384>>>(x, 0);
    mix_apply_kernel<<<NB * NW, 384>>>(x, 1);
    gemm_kernel<<<dim3(ND / BN, NBHW / BM), 256>>>(x, Wo, out);
}

// round 3
// speedup vs baseline: 1.9903x; 1.9903x over previous
#include <cuda_runtime.h>
#include <cstdint>

// Problem constants
#define NB   64
#define NH   32
#define NW   32
#define ND   384
#define NBHW (NB*NH*NW)          // 65536 rows

// Scratch (device globals; no allocation allowed)
__device__ float g_p[NBHW * 4];                 // [b,h,w][yh0,yh1,yw0,yw1]
__device__ float g_attn_h[NB * NW * 32 * 32];   // [b][w][h1][h2]
__device__ float g_attn_w[NB * NH * 32 * 32];   // [b][h][w1][w2]
__device__ float g_Yhw[(size_t)NBHW * ND];      // Yh + Yw
__device__ float g_Wco[ND * ND];                // Wo @ Wc
__device__ float g_bias[ND];                    // Wo @ bc + bo

// ---------------------------------------------------------------------------
// Wco[o][d] = sum_k Wo[o][k] * Wc[k][d]
__global__ void wco_kernel(const float* __restrict__ Wo, const float* __restrict__ Wc) {
    __shared__ float As[16][16];
    __shared__ float Bs[16][17];
    int o = blockIdx.y * 16 + threadIdx.y;
    int d = blockIdx.x * 16 + threadIdx.x;
    float acc = 0.f;
    for (int k0 = 0; k0 < ND; k0 += 16) {
        As[threadIdx.y][threadIdx.x] = Wo[o * ND + k0 + threadIdx.x];
        Bs[threadIdx.y][threadIdx.x] = Wc[(k0 + threadIdx.y) * ND + d];
        __syncthreads();
#pragma unroll
        for (int k = 0; k < 16; k++) acc += As[threadIdx.y][k] * Bs[k][threadIdx.x];
        __syncthreads();
    }
    g_Wco[o * ND + d] = acc;
}

// bias[o] = bo[o] + sum_k Wo[o][k]*bc[k]
__global__ void bias_kernel(const float* __restrict__ Wo, const float* __restrict__ bc,
                            const float* __restrict__ bo) {
    int o = threadIdx.x;
    float s = bo[o];
    for (int k = 0; k < ND; k++) s += Wo[o * ND + k] * bc[k];
    g_bias[o] = s;
}

// ---------------------------------------------------------------------------
// Projections
__global__ __launch_bounds__(256) void proj_kernel(
    const float* __restrict__ x,
    const float* __restrict__ W1h, const float* __restrict__ b1h,
    const float* __restrict__ W1w, const float* __restrict__ b1w) {
    __shared__ __align__(16) float sW[1536];
    int tid = threadIdx.x;
    for (int i = tid; i < 768; i += 256) sW[i] = W1h[i];
    for (int i = tid; i < 768; i += 256) sW[768 + i] = W1w[i];
    __syncthreads();
    int lane = tid & 31, warp = tid >> 5;
    int row = blockIdx.x * 8 + warp;
    const float4* xr = (const float4*)(x + (size_t)row * ND);
    const float4* w0 = (const float4*)(sW);
    const float4* w1 = (const float4*)(sW + 384);
    const float4* w2 = (const float4*)(sW + 768);
    const float4* w3 = (const float4*)(sW + 1152);
    float a0 = 0.f, a1 = 0.f, a2 = 0.f, a3 = 0.f;
#pragma unroll
    for (int j = 0; j < 3; j++) {
        float4 xv = xr[lane + j * 32];
        float4 v;
        v = w0[lane + j * 32]; a0 += xv.x*v.x + xv.y*v.y + xv.z*v.z + xv.w*v.w;
        v = w1[lane + j * 32]; a1 += xv.x*v.x + xv.y*v.y + xv.z*v.z + xv.w*v.w;
        v = w2[lane + j * 32]; a2 += xv.x*v.x + xv.y*v.y + xv.z*v.z + xv.w*v.w;
        v = w3[lane + j * 32]; a3 += xv.x*v.x + xv.y*v.y + xv.z*v.z + xv.w*v.w;
    }
#pragma unroll
    for (int off = 16; off; off >>= 1) {
        a0 += __shfl_xor_sync(~0u, a0, off);
        a1 += __shfl_xor_sync(~0u, a1, off);
        a2 += __shfl_xor_sync(~0u, a2, off);
        a3 += __shfl_xor_sync(~0u, a3, off);
    }
    if (lane == 0) {
        float* pp = g_p + (size_t)row * 4;
        pp[0] = a0 + b1h[0];
        pp[1] = a1 + b1h[1];
        pp[2] = a2 + b1w[0];
        pp[3] = a3 + b1w[1];
    }
}

// ---------------------------------------------------------------------------
// Grouped mix logits + softmax.
__global__ __launch_bounds__(1024) void attn_kernel(
    const float* __restrict__ W2, const float* __restrict__ b2, int which) {
    int blk = blockIdx.x;
    int b = blk >> 5, s = blk & 31;
    int tid = threadIdx.x;
    __shared__ float yv[64];
    if (tid < 64) {
        int e = tid >> 5, t = tid & 31;
        int h = which ? s : t;
        int w = which ? t : s;
        yv[tid] = g_p[(size_t)(((b * 32 + h) * 32 + w) << 2) + (which ? 2 : 0) + e];
    }
    __syncthreads();
    int g = tid >> 7;
    float z = b2[tid];
    const float* wr = W2 + tid * 8;
    const float* yb = yv + g * 8;
#pragma unroll
    for (int c = 0; c < 8; c++) z += yb[c] * wr[c];
    float m = z;
#pragma unroll
    for (int off = 16; off; off >>= 1) m = fmaxf(m, __shfl_xor_sync(~0u, m, off));
    float ez = __expf(z - m);
    float sum = ez;
#pragma unroll
    for (int off = 16; off; off >>= 1) sum += __shfl_xor_sync(~0u, sum, off);
    float* out = which ? g_attn_w : g_attn_h;
    out[(size_t)blk * 1024 + tid] = ez * (1.0f / sum);
}

// ---------------------------------------------------------------------------
// Apply attention mixes.
__global__ __launch_bounds__(384) void mix_apply_kernel(const float* __restrict__ x, int which) {
    __shared__ __align__(16) float Ast[32 * 32];  // Ast[j*32 + i]
    int blk = blockIdx.x;
    int b = blk >> 5, s = blk & 31;
    int tid = threadIdx.x;
    const float* attn = (which ? g_attn_h : g_attn_w) + (size_t)blk * 1024;
    for (int idx = tid; idx < 1024; idx += 384) {
        int i = idx >> 5, j = idx & 31;
        Ast[j * 32 + i] = attn[idx];
    }
    __syncthreads();

    const float* xp;
    size_t xstride;
    if (which == 0) { xp = x + (size_t)blk * (32 * ND) + tid; xstride = ND; }
    else            { xp = x + ((size_t)b * 1024 + s) * ND + tid; xstride = (size_t)32 * ND; }

    float acc[32];
#pragma unroll
    for (int i = 0; i < 32; i++) acc[i] = 0.f;

#pragma unroll 8
    for (int j = 0; j < 32; j++) {
        float xv = xp[(size_t)j * xstride];
        const float4* a4 = (const float4*)(Ast + j * 32);
#pragma unroll
        for (int i4 = 0; i4 < 8; i4++) {
            float4 a = a4[i4];
            acc[i4 * 4 + 0] += a.x * xv;
            acc[i4 * 4 + 1] += a.y * xv;
            acc[i4 * 4 + 2] += a.z * xv;
            acc[i4 * 4 + 3] += a.w * xv;
        }
    }
    if (which == 0) {
        float* yb = g_Yhw + (size_t)blk * (32 * ND) + tid;
#pragma unroll
        for (int i = 0; i < 32; i++) yb[(size_t)i * ND] = acc[i];
    } else {
        float* yb = g_Yhw + ((size_t)b * 1024 + s) * ND + tid;
#pragma unroll
        for (int i = 0; i < 32; i++) yb[(size_t)i * 32 * ND] += acc[i];
    }
}

// ---------------------------------------------------------------------------
// Final fused GEMM via mma.sync tf32 (family-portable; tcgen05 not compilable
// through this harness — PTX target is plain sm_103).
// out[m,o] = sum_d Yhw[m,d]*Wo[o,d] + sum_d x[m,d]*Wco[o,d] + bias[o]
// CTA tile 128x128, warps 2(M)x4(N), warp tile 64x32, BK=16, double buffer.
#define SROW 20   // smem row stride in floats (80B): conflict-free frag access

static __device__ __forceinline__ uint32_t s2u(const void* p) {
    uint32_t a;
    asm("{ .reg .u64 t; cvta.to.shared.u64 t, %1; cvt.u32.u64 %0, t; }" : "=r"(a) : "l"(p));
    return a;
}
static __device__ __forceinline__ void cp16(uint32_t dst, const float* src) {
    asm volatile("cp.async.cg.shared.global [%0], [%1], 16;" :: "r"(dst), "l"(src));
}
static __device__ __forceinline__ uint32_t f2tf(float f) {
    uint32_t r;
    asm("cvt.rna.tf32.f32 %0, %1;" : "=r"(r) : "f"(f));
    return r;
}
static __device__ __forceinline__ void mma1688(float* d, const uint32_t* a, const uint32_t* b) {
    asm volatile(
        "mma.sync.aligned.m16n8k8.row.col.f32.tf32.tf32.f32 "
        "{%0,%1,%2,%3},{%4,%5,%6,%7},{%8,%9},{%0,%1,%2,%3};"
        : "+f"(d[0]), "+f"(d[1]), "+f"(d[2]), "+f"(d[3])
        : "r"(a[0]), "r"(a[1]), "r"(a[2]), "r"(a[3]), "r"(b[0]), "r"(b[1]));
}

__global__ __launch_bounds__(256, 2) void gemm_mma_kernel(
    const float* __restrict__ x, const float* __restrict__ Wo, float* __restrict__ out) {
    __shared__ float sA[2][128 * SROW];
    __shared__ float sB[2][128 * SROW];

    int tid = threadIdx.x;
    int lane = tid & 31, warp = tid >> 5;
    int wm = warp >> 2, wn = warp & 3;       // warp coords: 2 x 4
    int g = lane >> 2, c = lane & 3;         // groupID, threadID_in_group
    int m0 = blockIdx.y * 128;
    int n0 = blockIdx.x * 128;

    float acc[4][4][4];
#pragma unroll
    for (int mi = 0; mi < 4; mi++)
#pragma unroll
        for (int ni = 0; ni < 4; ni++)
#pragma unroll
            for (int r = 0; r < 4; r++) acc[mi][ni][r] = 0.f;

    // chunk c (0..47): K=768 over two phases
    auto load_chunk = [&](int ch, int buf) {
        const float* A; const float* B; int ko;
        if (ch < 24) { A = g_Yhw + (size_t)m0 * ND; B = Wo + (size_t)n0 * ND;    ko = ch * 16; }
        else         { A = x     + (size_t)m0 * ND; B = g_Wco + (size_t)n0 * ND; ko = ch * 16 - 384; }
        uint32_t ab = s2u(&sA[buf][0]);
        uint32_t bb = s2u(&sB[buf][0]);
#pragma unroll
        for (int q = 0; q < 2; q++) {
            int f = tid + q * 256;           // 512 float4 per matrix
            int row = f >> 2, kg = f & 3;
            cp16(ab + row * (SROW * 4) + kg * 16, A + (size_t)row * ND + ko + kg * 4);
            cp16(bb + row * (SROW * 4) + kg * 16, B + (size_t)row * ND + ko + kg * 4);
        }
        asm volatile("cp.async.commit_group;" ::: "memory");
    };

    load_chunk(0, 0);

#pragma unroll 1
    for (int i = 0; i < 48; i++) {
        int buf = i & 1;
        if (i + 1 < 48) load_chunk(i + 1, buf ^ 1);
        if (i + 1 < 48) asm volatile("cp.async.wait_group 1;" ::: "memory");
        else            asm volatile("cp.async.wait_group 0;" ::: "memory");
        __syncthreads();

        const float* pA = &sA[buf][0];
        const float* pB = &sB[buf][0];
#pragma unroll
        for (int ks = 0; ks < 2; ks++) {
            int kb = ks * 8;
            uint32_t afr[4][4];
#pragma unroll
            for (int mi = 0; mi < 4; mi++) {
                int r0 = (wm * 64 + mi * 16 + g) * SROW + kb + c;
                afr[mi][0] = f2tf(pA[r0]);
                afr[mi][1] = f2tf(pA[r0 + 8 * SROW]);
                afr[mi][2] = f2tf(pA[r0 + 4]);
                afr[mi][3] = f2tf(pA[r0 + 8 * SROW + 4]);
            }
            uint32_t bfr[4][2];
#pragma unroll
            for (int ni = 0; ni < 4; ni++) {
                int r0 = (wn * 32 + ni * 8 + g) * SROW + kb + c;
                bfr[ni][0] = f2tf(pB[r0]);
                bfr[ni][1] = f2tf(pB[r0 + 4]);
            }
#pragma unroll
            for (int mi = 0; mi < 4; mi++)
#pragma unroll
                for (int ni = 0; ni < 4; ni++)
                    mma1688(acc[mi][ni], afr[mi], bfr[ni]);
        }
        __syncthreads();
    }

    // Epilogue: D layout m16n8: c0/c1 at (g, 2c/2c+1), c2/c3 at (g+8, ...)
#pragma unroll
    for (int ni = 0; ni < 4; ni++) {
        int col = n0 + wn * 32 + ni * 8 + 2 * c;
        float b0 = g_bias[col], b1 = g_bias[col + 1];
#pragma unroll
        for (int mi = 0; mi < 4; mi++) {
            int row = m0 + wm * 64 + mi * 16 + g;
            float2 v0 = {acc[mi][ni][0] + b0, acc[mi][ni][1] + b1};
            float2 v1 = {acc[mi][ni][2] + b0, acc[mi][ni][3] + b1};
            *(float2*)(out + (size_t)row * ND + col) = v0;
            *(float2*)(out + (size_t)(row + 8) * ND + col) = v1;
        }
    }
}

// ---------------------------------------------------------------------------
extern "C" void kernel_launch(void* const* d_in, const int* in_sizes, int n_in,
                              void* d_out, int out_size) {
    const float* x   = (const float*)d_in[0];
    const float* Wc  = (const float*)d_in[1];
    const float* bc  = (const float*)d_in[2];
    const float* Wo  = (const float*)d_in[3];
    const float* bo  = (const float*)d_in[4];
    const float* W1h = (const float*)d_in[5];
    const float* b1h = (const float*)d_in[6];
    const float* W2h = (const float*)d_in[7];
    const float* b2h = (const float*)d_in[8];
    const float* W1w = (const float*)d_in[9];
    const float* b1w = (const float*)d_in[10];
    const float* W2w = (const float*)d_in[11];
    const float* b2w = (const float*)d_in[12];
    float* out = (float*)d_out;

    wco_kernel<<<dim3(24, 24), dim3(16, 16)>>>(Wo, Wc);
    bias_kernel<<<1, 384>>>(Wo, bc, bo);
    proj_kernel<<<NBHW / 8, 256>>>(x, W1h, b1h, W1w, b1w);
    attn_kernel<<<NB * NW, 1024>>>(W2h, b2h, 0);
    attn_kernel<<<NB * NH, 1024>>>(W2w, b2w, 1);
    mix_apply_kernel<<<NB * NH, 384>>>(x, 0);
    mix_apply_kernel<<<NB * NW, 384>>>(x, 1);
    gemm_mma_kernel<<<dim3(ND / 128, NBHW / 128), 256>>>(x, Wo, out);
}